// round 3
// baseline (speedup 1.0000x reference)
#include <cuda_runtime.h>

#define DEVINLINE __device__ __forceinline__

constexpr int BATCH = 100;

// --- coefficient segment offsets (gates, in float4 units) ---
constexpr int OFF_C1L0 = 0;      // 16*4 = 64
constexpr int OFF_C1L1 = 64;     // 16*2 = 32
constexpr int OFF_C1L2 = 96;     // 16
constexpr int OFF_C2L0 = 112;    // 48*4 = 192
constexpr int OFF_C2L1 = 304;    // 96
constexpr int OFF_C2L2 = 400;    // 48
constexpr int OFF_C3L0 = 448;    // 144*4 = 576
constexpr int OFF_C3L1 = 1024;   // 288
constexpr int OFF_C3L2 = 1312;   // 144
constexpr int OFF_FC1  = 1456;   // 20480
constexpr int OFF_FC2  = 21936;  // 10240
constexpr int OFF_FC3  = 32176;  // 5120
constexpr int N_COEF   = 37296;

// --- scratch (device globals; no allocation allowed) ---
__device__ float4 g_coef[N_COEF];
__device__ float  g_p1[BATCH * 16 * 12 * 12];   // conv1 pooled
__device__ float  g_p2[BATCH * 48 * 6 * 6];     // conv2 pooled
__device__ float  g_p3[BATCH * 144 * 3 * 3];    // conv3 pooled (= fc input, 1296/row)
__device__ float  g_f1[BATCH * 20480];
__device__ float  g_f2[BATCH * 10240];

// ============================================================================
// Coefficient precompute: softmax over 16 logits -> (C, A, B, D) per gate.
//   op(a,b) = C + A*a + B*b + D*a*b
// ============================================================================
struct CoeffArgs {
    const float* w[12];
    int off[13];
};

__global__ void coeff_kernel(CoeffArgs args) {
    int tid = blockIdx.x * blockDim.x + threadIdx.x;
    if (tid >= N_COEF) return;
    int s = 0;
    #pragma unroll
    for (int i = 0; i < 11; i++)
        if (tid >= args.off[i + 1]) s = i + 1;
    int g = tid - args.off[s];
    const float* w = args.w[s] + (size_t)g * 16;

    float v[16];
    float mx = -1e30f;
    #pragma unroll
    for (int i = 0; i < 16; i++) { v[i] = w[i]; mx = fmaxf(mx, v[i]); }
    float sum = 0.f;
    #pragma unroll
    for (int i = 0; i < 16; i++) { v[i] = expf(v[i] - mx); sum += v[i]; }
    float inv = 1.0f / sum;
    #pragma unroll
    for (int i = 0; i < 16; i++) v[i] *= inv;

    float C = v[8] + v[9] + v[10] + v[11] + v[12] + v[13] + v[14] + v[15];
    float A = v[2] + v[3] + v[6] + v[7] - v[8] - v[9] - v[12] - v[13];
    float B = v[4] + v[5] + v[6] + v[7] - v[8] - v[9] - v[10] - v[11];
    float D = v[1] - v[2] - v[4] - 2.f * v[6] - v[7]
            + v[8] + 2.f * v[9] + v[11] + v[13] - v[14];
    g_coef[tid] = make_float4(C, A, B, D);
}

DEVINLINE float gate(float a, float b, float4 k) {
    // C + A*a + B*b + D*a*b
    return fmaf(a, fmaf(k.w, b, k.y), fmaf(k.z, b, k.x));
}

DEVINLINE float pick4(const float h[4], int i) {
    float r = h[0];
    r = (i == 1) ? h[1] : r;
    r = (i == 2) ? h[2] : r;
    r = (i == 3) ? h[3] : r;
    return r;
}
DEVINLINE float pick2(const float h[2], int i) {
    return (i == 1) ? h[1] : h[0];
}

// ============================================================================
// Fused conv(logic-tree) + 2x2 max-pool.
// One thread = one (b, f, pooled_i, pooled_j) output.
// ============================================================================
template <int CIN, int KS, int PAD, int F, int HIN, int WIN, int OH, int OW, bool BIN>
__global__ void conv_kernel(const float* __restrict__ in,
                            const int* __restrict__ i0,
                            const int* __restrict__ i1,
                            const int* __restrict__ i2,
                            int coff0, int coff1, int coff2,
                            float* __restrict__ out) {
    constexpr int POH = OH / 2, POW = OW / 2;
    int tid = blockIdx.x * blockDim.x + threadIdx.x;
    constexpr int TOTAL = BATCH * F * POH * POW;
    if (tid >= TOTAL) return;

    int pj = tid % POW;
    int t  = tid / POW;
    int pi = t % POH; t /= POH;
    int f  = t % F;
    int b  = t / F;

    // per-filter tree topology + fused gate coefficients
    int a0[4], b0[4]; float4 k0[4];
    #pragma unroll
    for (int g = 0; g < 4; g++) {
        a0[g] = __ldg(i0 + f * 4 + g);
        b0[g] = __ldg(i0 + F * 4 + f * 4 + g);
        k0[g] = g_coef[coff0 + f * 4 + g];
    }
    int a1[2], b1[2]; float4 k1[2];
    #pragma unroll
    for (int g = 0; g < 2; g++) {
        a1[g] = __ldg(i1 + f * 2 + g);
        b1[g] = __ldg(i1 + F * 2 + f * 2 + g);
        k1[g] = g_coef[coff1 + f * 2 + g];
    }
    int a2 = __ldg(i2 + f), b2 = __ldg(i2 + F + f);
    float4 k2 = g_coef[coff2 + f];

    const float* inb = in + (size_t)b * CIN * HIN * WIN;

    float m = -1e30f;
    #pragma unroll
    for (int di = 0; di < 2; di++) {
        #pragma unroll
        for (int dj = 0; dj < 2; dj++) {
            int oi = 2 * pi + di, oj = 2 * pj + dj;
            float h0[4];
            #pragma unroll
            for (int g = 0; g < 4; g++) {
                float av, bv;
                {
                    int tt = a0[g];
                    int c = tt / (KS * KS); int r = tt - c * KS * KS;
                    int ki = r / KS, kj = r - (r / KS) * KS;
                    int ii = oi + ki - PAD, jj = oj + kj - PAD;
                    if (PAD != 0 && (ii < 0 || ii >= HIN || jj < 0 || jj >= WIN)) {
                        av = 0.f;
                    } else {
                        av = __ldg(inb + (c * HIN + ii) * WIN + jj);
                        if (BIN) av = (av > 0.5f) ? 1.f : 0.f;
                    }
                }
                {
                    int tt = b0[g];
                    int c = tt / (KS * KS); int r = tt - c * KS * KS;
                    int ki = r / KS, kj = r - (r / KS) * KS;
                    int ii = oi + ki - PAD, jj = oj + kj - PAD;
                    if (PAD != 0 && (ii < 0 || ii >= HIN || jj < 0 || jj >= WIN)) {
                        bv = 0.f;
                    } else {
                        bv = __ldg(inb + (c * HIN + ii) * WIN + jj);
                        if (BIN) bv = (bv > 0.5f) ? 1.f : 0.f;
                    }
                }
                h0[g] = gate(av, bv, k0[g]);
            }
            float h1[2];
            #pragma unroll
            for (int g = 0; g < 2; g++)
                h1[g] = gate(pick4(h0, a1[g]), pick4(h0, b1[g]), k1[g]);
            float v = gate(pick2(h1, a2), pick2(h1, b2), k2);
            m = fmaxf(m, v);
        }
    }
    out[tid] = m;
}

// ============================================================================
// FC logic layer: one thread = one (b, o) gate.
// ============================================================================
template <int DIN, int DOUT>
__global__ void fc_kernel(const float* __restrict__ in,
                          const int* __restrict__ idx,
                          int coff,
                          float* __restrict__ out) {
    int tid = blockIdx.x * blockDim.x + threadIdx.x;
    if (tid >= BATCH * DOUT) return;
    int o = tid % DOUT;
    int b = tid / DOUT;
    int ia = __ldg(idx + o);
    int ib = __ldg(idx + DOUT + o);
    float4 k = g_coef[coff + o];
    const float* row = in + (size_t)b * DIN;
    out[tid] = gate(__ldg(row + ia), __ldg(row + ib), k);
}

// ============================================================================
// FC3 + GroupSum(k=10, tau=30) fused. grid = (B, 10), block = 512.
// ============================================================================
__global__ void fc3_sum_kernel(const int* __restrict__ idx,
                               float* __restrict__ out) {
    int b = blockIdx.x, grp = blockIdx.y;
    int t = threadIdx.x;                 // 0..511
    int o = grp * 512 + t;
    const float* row = g_f2 + (size_t)b * 10240;
    int ia = __ldg(idx + o);
    int ib = __ldg(idx + 5120 + o);
    float4 k = g_coef[OFF_FC3 + o];
    float v = gate(__ldg(row + ia), __ldg(row + ib), k);

    __shared__ float sdata[16];
    #pragma unroll
    for (int off = 16; off; off >>= 1) v += __shfl_down_sync(0xffffffffu, v, off);
    if ((t & 31) == 0) sdata[t >> 5] = v;
    __syncthreads();
    if (t < 16) {
        float s = sdata[t];
        #pragma unroll
        for (int off = 8; off; off >>= 1) s += __shfl_down_sync(0xffffu, s, off);
        if (t == 0) out[b * 10 + grp] = s / 30.0f;
    }
}

// ============================================================================
// Launch
// ============================================================================
extern "C" void kernel_launch(void* const* d_in, const int* in_sizes, int n_in,
                              void* d_out, int out_size) {
    const float* x     = (const float*)d_in[0];
    const int*   c1i0  = (const int*)  d_in[1];
    const float* c1w0  = (const float*)d_in[2];
    const int*   c1i1  = (const int*)  d_in[3];
    const float* c1w1  = (const float*)d_in[4];
    const int*   c1i2  = (const int*)  d_in[5];
    const float* c1w2  = (const float*)d_in[6];
    const int*   c2i0  = (const int*)  d_in[7];
    const float* c2w0  = (const float*)d_in[8];
    const int*   c2i1  = (const int*)  d_in[9];
    const float* c2w1  = (const float*)d_in[10];
    const int*   c2i2  = (const int*)  d_in[11];
    const float* c2w2  = (const float*)d_in[12];
    const int*   c3i0  = (const int*)  d_in[13];
    const float* c3w0  = (const float*)d_in[14];
    const int*   c3i1  = (const int*)  d_in[15];
    const float* c3w1  = (const float*)d_in[16];
    const int*   c3i2  = (const int*)  d_in[17];
    const float* c3w2  = (const float*)d_in[18];
    const int*   fc1i  = (const int*)  d_in[19];
    const float* fc1w  = (const float*)d_in[20];
    const int*   fc2i  = (const int*)  d_in[21];
    const float* fc2w  = (const float*)d_in[22];
    const int*   fc3i  = (const int*)  d_in[23];
    const float* fc3w  = (const float*)d_in[24];
    float* out = (float*)d_out;

    // scratch addresses
    float *p1, *p2, *p3, *f1, *f2;
    cudaGetSymbolAddress((void**)&p1, g_p1);
    cudaGetSymbolAddress((void**)&p2, g_p2);
    cudaGetSymbolAddress((void**)&p3, g_p3);
    cudaGetSymbolAddress((void**)&f1, g_f1);
    cudaGetSymbolAddress((void**)&f2, g_f2);

    // 1) fused coefficient precompute (all 12 weight tensors)
    CoeffArgs ca;
    const float* ws[12] = {c1w0, c1w1, c1w2, c2w0, c2w1, c2w2,
                           c3w0, c3w1, c3w2, fc1w, fc2w, fc3w};
    int offs[13] = {OFF_C1L0, OFF_C1L1, OFF_C1L2, OFF_C2L0, OFF_C2L1, OFF_C2L2,
                    OFF_C3L0, OFF_C3L1, OFF_C3L2, OFF_FC1, OFF_FC2, OFF_FC3, N_COEF};
    for (int i = 0; i < 12; i++) ca.w[i] = ws[i];
    for (int i = 0; i < 13; i++) ca.off[i] = offs[i];
    coeff_kernel<<<(N_COEF + 255) / 256, 256>>>(ca);

    // 2) conv1 (binarize fused) + pool: [100,1,28,28] -> [100,16,12,12]
    {
        constexpr int TOT = BATCH * 16 * 12 * 12;
        conv_kernel<1, 5, 0, 16, 28, 28, 24, 24, true>
            <<<(TOT + 255) / 256, 256>>>(x, c1i0, c1i1, c1i2,
                                         OFF_C1L0, OFF_C1L1, OFF_C1L2, p1);
    }
    // 3) conv2 + pool: [100,16,12,12] -> [100,48,6,6]
    {
        constexpr int TOT = BATCH * 48 * 6 * 6;
        conv_kernel<16, 3, 1, 48, 12, 12, 12, 12, false>
            <<<(TOT + 255) / 256, 256>>>(p1, c2i0, c2i1, c2i2,
                                         OFF_C2L0, OFF_C2L1, OFF_C2L2, p2);
    }
    // 4) conv3 + pool: [100,48,6,6] -> [100,144,3,3]
    {
        constexpr int TOT = BATCH * 144 * 3 * 3;
        conv_kernel<48, 3, 1, 144, 6, 6, 6, 6, false>
            <<<(TOT + 255) / 256, 256>>>(p2, c3i0, c3i1, c3i2,
                                         OFF_C3L0, OFF_C3L1, OFF_C3L2, p3);
    }
    // 5) fc1: 1296 -> 20480
    fc_kernel<1296, 20480><<<(BATCH * 20480 + 255) / 256, 256>>>(p3, fc1i, OFF_FC1, f1);
    // 6) fc2: 20480 -> 10240
    fc_kernel<20480, 10240><<<(BATCH * 10240 + 255) / 256, 256>>>(f1, fc2i, OFF_FC2, f2);
    // 7) fc3 + group sum -> [100, 10]
    {
        dim3 grid(BATCH, 10);
        fc3_sum_kernel<<<grid, 512>>>(fc3i, out);
    }
    (void)in_sizes; (void)n_in; (void)out_size;
}